// round 3
// baseline (speedup 1.0000x reference)
#include <cuda_runtime.h>
#include <math.h>

#define NW 512      // num windows (B_)
#define LQ 256      // tokens per window (L)
#define CD 128      // channels (C)
#define NH 4        // heads
#define HD 32       // head dim
#define MT 1575     // rel table rows (15*15*7)

// ---------------- device scratch (no runtime allocation allowed) ----------------
static __device__ float g_bias_table[MT * NH];                    // (M, H)
static __device__ float g_bias[NH * LQ * LQ];                     // 16*sigmoid, (H, L, L) — 1 MB
static __device__ float g_q[(size_t)NW * NH * LQ * HD];           // normalized+scaled q, (B,H,L,hd)
static __device__ float g_k[(size_t)NW * NH * LQ * HD];           // normalized k
static __device__ float g_v[(size_t)NW * NH * LQ * HD];           // v
static __device__ float g_att[(size_t)NW * LQ * CD];              // attention output (B,L,C)

// ---------------- CPB MLP: bias_table[m][h] = (relu(t @ w1^T + b1) @ w2^T)[m][h] ----
// 32 m per block, 8 u-lanes per m, shuffle-reduce.
__global__ void cpb_kernel(const float* __restrict__ table, const float* __restrict__ w1,
                           const float* __restrict__ b1, const float* __restrict__ w2)
{
    int t  = threadIdx.x;
    int mi = t >> 3, ui = t & 7;
    int m  = blockIdx.x * 32 + mi;
    float a0 = 0.f, a1 = 0.f, a2 = 0.f, a3 = 0.f;
    if (m < MT) {
        float t0 = table[m*3+0], t1 = table[m*3+1], t2 = table[m*3+2];
        for (int u = ui; u < 512; u += 8) {
            float hid = fmaf(w1[u*3+0], t0, fmaf(w1[u*3+1], t1, fmaf(w1[u*3+2], t2, b1[u])));
            hid = fmaxf(hid, 0.f);
            a0 = fmaf(hid, w2[u],        a0);
            a1 = fmaf(hid, w2[512+u],    a1);
            a2 = fmaf(hid, w2[1024+u],   a2);
            a3 = fmaf(hid, w2[1536+u],   a3);
        }
    }
    #pragma unroll
    for (int off = 4; off >= 1; off >>= 1) {
        a0 += __shfl_down_sync(0xffffffffu, a0, off, 8);
        a1 += __shfl_down_sync(0xffffffffu, a1, off, 8);
        a2 += __shfl_down_sync(0xffffffffu, a2, off, 8);
        a3 += __shfl_down_sync(0xffffffffu, a3, off, 8);
    }
    if (ui == 0 && m < MT) {
        g_bias_table[m*NH+0] = a0;
        g_bias_table[m*NH+1] = a1;
        g_bias_table[m*NH+2] = a2;
        g_bias_table[m*NH+3] = a3;
    }
}

// ---------------- bias gather + 16*sigmoid ----------------
__global__ void bias_gather_kernel(const int* __restrict__ idx)
{
    int i = blockIdx.x * blockDim.x + threadIdx.x;   // over NH*LQ*LQ = 262144
    if (i >= NH * LQ * LQ) return;
    int h  = i >> 16;
    int ij = i & 65535;
    float x = g_bias_table[idx[ij] * NH + h];
    g_bias[i] = 16.f / (1.f + __expf(-x));
}

// ---------------- QKV GEMM (64x128 tile, K=128 in 4 chunks) + fused bias/normalize ----
// grid.x = 2048 row tiles, grid.y = tensor (0=q, 1=k, 2=v)
__global__ __launch_bounds__(256) void qkv_gemm_kernel(
    const float* __restrict__ A,      // x flattened (131072, 128)
    const float* __restrict__ W,      // qkv_w (384, 128)
    const float* __restrict__ qb,     // (128,)
    const float* __restrict__ vb,     // (128,)
    const float* __restrict__ ls)     // logit_scale (4,)
{
    __shared__ float sm[8448];        // stage: As[64*36] + Ws[128*36] = 6912f; epi: S[64*132]=8448f
    __shared__ float fac[64 * 4];
    float* As = sm;                   // 64 x 36
    float* Ws = sm + 64*36;           // 128 x 36
    const int tid = threadIdx.x;
    const int tmode = blockIdx.y;     // 0 q, 1 k, 2 v
    const int r0 = blockIdx.x * 64;
    const int tr = tid >> 4, tc = tid & 15;

    float acc[4][8];
    #pragma unroll
    for (int r = 0; r < 4; r++)
        #pragma unroll
        for (int i = 0; i < 8; i++) acc[r][i] = 0.f;

    const float* Wbase = W + tmode * 128 * 128;

    for (int kc = 0; kc < 4; kc++) {
        const int k0 = kc * 32;
        // stage A chunk: 64x32 = 512 float4
        {
            int f = tid;
            #pragma unroll
            for (int rep = 0; rep < 2; rep++, f += 256) {
                int row = f >> 3, c4 = f & 7;
                float4 v = *(const float4*)(A + (size_t)(r0 + row) * CD + k0 + c4 * 4);
                float* d = As + row * 36 + c4 * 4;
                d[0] = v.x; d[1] = v.y; d[2] = v.z; d[3] = v.w;
            }
        }
        // stage W chunk: 128x32 = 1024 float4
        {
            int f = tid;
            #pragma unroll
            for (int rep = 0; rep < 4; rep++, f += 256) {
                int row = f >> 3, c4 = f & 7;
                float4 v = *(const float4*)(Wbase + row * CD + k0 + c4 * 4);
                float* d = Ws + row * 36 + c4 * 4;
                d[0] = v.x; d[1] = v.y; d[2] = v.z; d[3] = v.w;
            }
        }
        __syncthreads();
        #pragma unroll
        for (int k4 = 0; k4 < 8; k4++) {
            float4 a[4], b[8];
            #pragma unroll
            for (int r = 0; r < 4; r++) a[r] = *(const float4*)(As + (tr*4 + r) * 36 + k4 * 4);
            #pragma unroll
            for (int i = 0; i < 8; i++) b[i] = *(const float4*)(Ws + (tc + 16*i) * 36 + k4 * 4);
            #pragma unroll
            for (int r = 0; r < 4; r++)
                #pragma unroll
                for (int i = 0; i < 8; i++) {
                    acc[r][i] = fmaf(a[r].x, b[i].x, acc[r][i]);
                    acc[r][i] = fmaf(a[r].y, b[i].y, acc[r][i]);
                    acc[r][i] = fmaf(a[r].z, b[i].z, acc[r][i]);
                    acc[r][i] = fmaf(a[r].w, b[i].w, acc[r][i]);
                }
        }
        __syncthreads();
    }

    // epilogue: add bias, stash tile in smem, compute per-(row,head) factors, write out
    float* S = sm;   // 64 x 132
    #pragma unroll
    for (int r = 0; r < 4; r++)
        #pragma unroll
        for (int i = 0; i < 8; i++) {
            int col = tc + 16*i;
            float bias = (tmode == 0) ? qb[col] : (tmode == 2) ? vb[col] : 0.f;
            S[(tr*4 + r) * 132 + col] = acc[r][i] + bias;
        }
    __syncthreads();
    {
        int row = tid >> 2, hh = tid & 3;
        float f;
        if (tmode == 2) {
            f = 1.f;
        } else {
            const float* p = S + row * 132 + hh * 32;
            float ss = 0.f;
            #pragma unroll
            for (int d = 0; d < 32; d++) ss = fmaf(p[d], p[d], ss);
            f = 1.f / fmaxf(sqrtf(ss), 1e-12f);
            if (tmode == 0) f *= expf(fminf(ls[hh], 4.60517018598809136804f)); // log(100)
        }
        fac[tid] = f;
    }
    __syncthreads();

    float* out = (tmode == 0) ? g_q : (tmode == 1) ? g_k : g_v;
    #pragma unroll
    for (int r = 0; r < 4; r++) {
        int row = tr*4 + r;
        int gr  = r0 + row;
        int b   = gr >> 8, l = gr & 255;
        #pragma unroll
        for (int i = 0; i < 8; i++) {
            int col = tc + 16*i;
            int hh = col >> 5, d = col & 31;
            out[(size_t)(((b * NH + hh) * LQ) + l) * HD + d] = S[row * 132 + col] * fac[row * 4 + hh];
        }
    }
}

// ---------------- flash-style attention per (window, head) ----------------
// one CTA per (b,h); 256 threads, one query row per thread; k,v in smem.
// All inner-loop smem reads are warp-wide broadcasts of row j -> conflict-free
// with NO padding (broadcast == N=1), so stride is exactly HD=32.
__global__ __launch_bounds__(256, 3) void attn_kernel()
{
    extern __shared__ float sh[];
    float* ks = sh;                 // 256 x 32
    float* vs = sh + LQ * HD;       // 256 x 32
    const int bh = blockIdx.x;      // b*4 + h
    const int h  = bh & 3;
    const int b  = bh >> 2;
    const float* qg = g_q + (size_t)bh * LQ * HD;
    const float* kg = g_k + (size_t)bh * LQ * HD;
    const float* vg = g_v + (size_t)bh * LQ * HD;
    const int tid = threadIdx.x;

    // stage k and v (2048 float4 each total); layout matches gmem exactly
    #pragma unroll
    for (int rep = 0; rep < 8; rep++) {
        int f = tid + rep * 256;            // float4 index
        *(float4*)(ks + (size_t)f * 4) = *(const float4*)(kg + (size_t)f * 4);
        *(float4*)(vs + (size_t)f * 4) = *(const float4*)(vg + (size_t)f * 4);
    }
    // query row into registers
    float4 q[8];
    #pragma unroll
    for (int d4 = 0; d4 < 8; d4++) q[d4] = *(const float4*)(qg + (size_t)tid * HD + d4 * 4);
    __syncthreads();

    const float* bptr = g_bias + h * (LQ * LQ) + tid * LQ;

    float m = -1e30f, lsum = 0.f;
    float acc[32];
    #pragma unroll
    for (int d = 0; d < 32; d++) acc[d] = 0.f;

    // bias register window: prefetch one float4 ahead
    float4 bwin = *(const float4*)(bptr);

    #pragma unroll 1
    for (int j4 = 0; j4 < LQ / 4; j4++) {
        float4 bcur = bwin;
        if (j4 + 1 < LQ / 4) bwin = *(const float4*)(bptr + (j4 + 1) * 4);
        #pragma unroll
        for (int jj = 0; jj < 4; jj++) {
            int j = j4 * 4 + jj;
            float s0 = 0.f, s1 = 0.f, s2 = 0.f, s3 = 0.f;
            #pragma unroll
            for (int d4 = 0; d4 < 8; d4++) {
                float4 kk = *(const float4*)(ks + j * HD + d4 * 4);
                s0 = fmaf(q[d4].x, kk.x, s0);
                s1 = fmaf(q[d4].y, kk.y, s1);
                s2 = fmaf(q[d4].z, kk.z, s2);
                s3 = fmaf(q[d4].w, kk.w, s3);
            }
            float bj = (jj == 0) ? bcur.x : (jj == 1) ? bcur.y : (jj == 2) ? bcur.z : bcur.w;
            float s = (s0 + s1) + (s2 + s3) + bj;

            float mn = fmaxf(m, s);
            float p  = __expf(s - mn);
            if (mn > m) {
                float c = __expf(m - mn);
                lsum *= c;
                #pragma unroll
                for (int d = 0; d < 32; d++) acc[d] *= c;
                m = mn;
            }
            lsum += p;
            #pragma unroll
            for (int d4 = 0; d4 < 8; d4++) {
                float4 vv = *(const float4*)(vs + j * HD + d4 * 4);
                acc[d4*4+0] = fmaf(p, vv.x, acc[d4*4+0]);
                acc[d4*4+1] = fmaf(p, vv.y, acc[d4*4+1]);
                acc[d4*4+2] = fmaf(p, vv.z, acc[d4*4+2]);
                acc[d4*4+3] = fmaf(p, vv.w, acc[d4*4+3]);
            }
        }
    }

    float inv = 1.f / lsum;
    float* op = g_att + ((size_t)(b * LQ + tid)) * CD + h * HD;
    #pragma unroll
    for (int d4 = 0; d4 < 8; d4++) {
        float4 o;
        o.x = acc[d4*4+0] * inv;
        o.y = acc[d4*4+1] * inv;
        o.z = acc[d4*4+2] * inv;
        o.w = acc[d4*4+3] * inv;
        *(float4*)(op + d4 * 4) = o;
    }
}

// ---------------- projection GEMM: out = att @ proj_w^T + proj_b ----------------
__global__ __launch_bounds__(256) void proj_gemm_kernel(
    const float* __restrict__ W,     // proj_w (128,128)
    const float* __restrict__ pb,    // (128,)
    float* __restrict__ out)
{
    __shared__ float sm[64*36 + 128*36];
    float* As = sm;
    float* Ws = sm + 64*36;
    const int tid = threadIdx.x;
    const int r0 = blockIdx.x * 64;
    const int tr = tid >> 4, tc = tid & 15;
    const float* A = g_att;

    float acc[4][8];
    #pragma unroll
    for (int r = 0; r < 4; r++)
        #pragma unroll
        for (int i = 0; i < 8; i++) acc[r][i] = 0.f;

    for (int kc = 0; kc < 4; kc++) {
        const int k0 = kc * 32;
        {
            int f = tid;
            #pragma unroll
            for (int rep = 0; rep < 2; rep++, f += 256) {
                int row = f >> 3, c4 = f & 7;
                float4 v = *(const float4*)(A + (size_t)(r0 + row) * CD + k0 + c4 * 4);
                float* d = As + row * 36 + c4 * 4;
                d[0] = v.x; d[1] = v.y; d[2] = v.z; d[3] = v.w;
            }
        }
        {
            int f = tid;
            #pragma unroll
            for (int rep = 0; rep < 4; rep++, f += 256) {
                int row = f >> 3, c4 = f & 7;
                float4 v = *(const float4*)(W + row * CD + k0 + c4 * 4);
                float* d = Ws + row * 36 + c4 * 4;
                d[0] = v.x; d[1] = v.y; d[2] = v.z; d[3] = v.w;
            }
        }
        __syncthreads();
        #pragma unroll
        for (int k4 = 0; k4 < 8; k4++) {
            float4 a[4], b[8];
            #pragma unroll
            for (int r = 0; r < 4; r++) a[r] = *(const float4*)(As + (tr*4 + r) * 36 + k4 * 4);
            #pragma unroll
            for (int i = 0; i < 8; i++) b[i] = *(const float4*)(Ws + (tc + 16*i) * 36 + k4 * 4);
            #pragma unroll
            for (int r = 0; r < 4; r++)
                #pragma unroll
                for (int i = 0; i < 8; i++) {
                    acc[r][i] = fmaf(a[r].x, b[i].x, acc[r][i]);
                    acc[r][i] = fmaf(a[r].y, b[i].y, acc[r][i]);
                    acc[r][i] = fmaf(a[r].z, b[i].z, acc[r][i]);
                    acc[r][i] = fmaf(a[r].w, b[i].w, acc[r][i]);
                }
        }
        __syncthreads();
    }

    #pragma unroll
    for (int r = 0; r < 4; r++) {
        int gr = r0 + tr*4 + r;
        #pragma unroll
        for (int i = 0; i < 8; i++) {
            int col = tc + 16*i;
            out[(size_t)gr * CD + col] = acc[r][i] + pb[col];
        }
    }
}

// ---------------- launch ----------------
extern "C" void kernel_launch(void* const* d_in, const int* in_sizes, int n_in,
                              void* d_out, int out_size)
{
    (void)in_sizes; (void)n_in; (void)out_size;
    const float* x       = (const float*)d_in[0];
    const float* qkv_w   = (const float*)d_in[1];
    const float* q_bias  = (const float*)d_in[2];
    const float* v_bias  = (const float*)d_in[3];
    const float* lscale  = (const float*)d_in[4];
    const float* cpb_w1  = (const float*)d_in[5];
    const float* cpb_b1  = (const float*)d_in[6];
    const float* cpb_w2  = (const float*)d_in[7];
    const float* proj_w  = (const float*)d_in[8];
    const float* proj_b  = (const float*)d_in[9];
    const float* rtable  = (const float*)d_in[10];
    const int*   ridx    = (const int*)d_in[11];
    float* out = (float*)d_out;

    static const int attn_smem = 2 * LQ * HD * 4;   // 65536 bytes
    cudaFuncSetAttribute(attn_kernel, cudaFuncAttributeMaxDynamicSharedMemorySize, attn_smem);

    cpb_kernel<<<(MT + 31) / 32, 256>>>(rtable, cpb_w1, cpb_b1, cpb_w2);
    bias_gather_kernel<<<(NH * LQ * LQ) / 256, 256>>>(ridx);
    qkv_gemm_kernel<<<dim3((NW * LQ) / 64, 3), 256>>>(x, qkv_w, q_bias, v_bias, lscale);
    attn_kernel<<<NW * NH, 256, attn_smem>>>();
    proj_gemm_kernel<<<(NW * LQ) / 64, 256>>>(proj_w, proj_b, out);
}

// round 4
// speedup vs baseline: 1.2094x; 1.2094x over previous
#include <cuda_runtime.h>
#include <math.h>

#define NW 512      // num windows (B_)
#define LQ 256      // tokens per window (L)
#define CD 128      // channels (C)
#define NH 4        // heads
#define HD 32       // head dim
#define MT 1575     // rel table rows (15*15*7)

// ---------------- packed f32x2 helpers (Blackwell PTX-only ops) ----------------
__device__ __forceinline__ unsigned long long f2pack(float lo, float hi) {
    unsigned long long r;
    asm("mov.b64 %0, {%1, %2};" : "=l"(r) : "f"(lo), "f"(hi));
    return r;
}
__device__ __forceinline__ void f2unpack(unsigned long long v, float& lo, float& hi) {
    asm("mov.b64 {%0, %1}, %2;" : "=f"(lo), "=f"(hi) : "l"(v));
}
__device__ __forceinline__ unsigned long long f2fma(unsigned long long a,
                                                    unsigned long long b,
                                                    unsigned long long c) {
    unsigned long long d;
    asm("fma.rn.f32x2 %0, %1, %2, %3;" : "=l"(d) : "l"(a), "l"(b), "l"(c));
    return d;
}
__device__ __forceinline__ unsigned long long f2add(unsigned long long a,
                                                    unsigned long long b) {
    unsigned long long d;
    asm("add.rn.f32x2 %0, %1, %2;" : "=l"(d) : "l"(a), "l"(b));
    return d;
}
__device__ __forceinline__ unsigned long long f2mul(unsigned long long a,
                                                    unsigned long long b) {
    unsigned long long d;
    asm("mul.rn.f32x2 %0, %1, %2;" : "=l"(d) : "l"(a), "l"(b));
    return d;
}

// ---------------- device scratch (no runtime allocation allowed) ----------------
static __device__ float g_bias_table[MT * NH];                    // (M, H)
static __device__ float g_bias[NH * LQ * LQ];                     // 16*sigmoid, (H, L, L) — 1 MB
static __device__ float g_q[(size_t)NW * NH * LQ * HD];           // normalized+scaled q, (B,H,L,hd)
static __device__ float g_k[(size_t)NW * NH * LQ * HD];           // normalized k
static __device__ float g_v[(size_t)NW * NH * LQ * HD];           // v
static __device__ float g_att[(size_t)NW * LQ * CD];              // attention output (B,L,C)

// ---------------- CPB MLP ----------------
__global__ void cpb_kernel(const float* __restrict__ table, const float* __restrict__ w1,
                           const float* __restrict__ b1, const float* __restrict__ w2)
{
    int t  = threadIdx.x;
    int mi = t >> 3, ui = t & 7;
    int m  = blockIdx.x * 32 + mi;
    float a0 = 0.f, a1 = 0.f, a2 = 0.f, a3 = 0.f;
    if (m < MT) {
        float t0 = table[m*3+0], t1 = table[m*3+1], t2 = table[m*3+2];
        for (int u = ui; u < 512; u += 8) {
            float hid = fmaf(w1[u*3+0], t0, fmaf(w1[u*3+1], t1, fmaf(w1[u*3+2], t2, b1[u])));
            hid = fmaxf(hid, 0.f);
            a0 = fmaf(hid, w2[u],        a0);
            a1 = fmaf(hid, w2[512+u],    a1);
            a2 = fmaf(hid, w2[1024+u],   a2);
            a3 = fmaf(hid, w2[1536+u],   a3);
        }
    }
    #pragma unroll
    for (int off = 4; off >= 1; off >>= 1) {
        a0 += __shfl_down_sync(0xffffffffu, a0, off, 8);
        a1 += __shfl_down_sync(0xffffffffu, a1, off, 8);
        a2 += __shfl_down_sync(0xffffffffu, a2, off, 8);
        a3 += __shfl_down_sync(0xffffffffu, a3, off, 8);
    }
    if (ui == 0 && m < MT) {
        g_bias_table[m*NH+0] = a0;
        g_bias_table[m*NH+1] = a1;
        g_bias_table[m*NH+2] = a2;
        g_bias_table[m*NH+3] = a3;
    }
}

// ---------------- bias gather + 16*sigmoid ----------------
__global__ void bias_gather_kernel(const int* __restrict__ idx)
{
    int i = blockIdx.x * blockDim.x + threadIdx.x;   // over NH*LQ*LQ = 262144
    if (i >= NH * LQ * LQ) return;
    int h  = i >> 16;
    int ij = i & 65535;
    float x = g_bias_table[idx[ij] * NH + h];
    g_bias[i] = 16.f / (1.f + __expf(-x));
}

// ---------------- QKV GEMM (64x128 tile) + fused bias/normalize ----------------
__global__ __launch_bounds__(256) void qkv_gemm_kernel(
    const float* __restrict__ A,      // x flattened (131072, 128)
    const float* __restrict__ W,      // qkv_w (384, 128)
    const float* __restrict__ qb,     // (128,)
    const float* __restrict__ vb,     // (128,)
    const float* __restrict__ ls)     // logit_scale (4,)
{
    __shared__ float sm[8448];
    __shared__ float fac[64 * 4];
    float* As = sm;                   // 64 x 36
    float* Ws = sm + 64*36;           // 128 x 36
    const int tid = threadIdx.x;
    const int tmode = blockIdx.y;     // 0 q, 1 k, 2 v
    const int r0 = blockIdx.x * 64;
    const int tr = tid >> 4, tc = tid & 15;

    float acc[4][8];
    #pragma unroll
    for (int r = 0; r < 4; r++)
        #pragma unroll
        for (int i = 0; i < 8; i++) acc[r][i] = 0.f;

    const float* Wbase = W + tmode * 128 * 128;

    for (int kc = 0; kc < 4; kc++) {
        const int k0 = kc * 32;
        {
            int f = tid;
            #pragma unroll
            for (int rep = 0; rep < 2; rep++, f += 256) {
                int row = f >> 3, c4 = f & 7;
                float4 v = *(const float4*)(A + (size_t)(r0 + row) * CD + k0 + c4 * 4);
                float* d = As + row * 36 + c4 * 4;
                d[0] = v.x; d[1] = v.y; d[2] = v.z; d[3] = v.w;
            }
        }
        {
            int f = tid;
            #pragma unroll
            for (int rep = 0; rep < 4; rep++, f += 256) {
                int row = f >> 3, c4 = f & 7;
                float4 v = *(const float4*)(Wbase + row * CD + k0 + c4 * 4);
                float* d = Ws + row * 36 + c4 * 4;
                d[0] = v.x; d[1] = v.y; d[2] = v.z; d[3] = v.w;
            }
        }
        __syncthreads();
        #pragma unroll
        for (int k4 = 0; k4 < 8; k4++) {
            float4 a[4], b[8];
            #pragma unroll
            for (int r = 0; r < 4; r++) a[r] = *(const float4*)(As + (tr*4 + r) * 36 + k4 * 4);
            #pragma unroll
            for (int i = 0; i < 8; i++) b[i] = *(const float4*)(Ws + (tc + 16*i) * 36 + k4 * 4);
            #pragma unroll
            for (int r = 0; r < 4; r++)
                #pragma unroll
                for (int i = 0; i < 8; i++) {
                    acc[r][i] = fmaf(a[r].x, b[i].x, acc[r][i]);
                    acc[r][i] = fmaf(a[r].y, b[i].y, acc[r][i]);
                    acc[r][i] = fmaf(a[r].z, b[i].z, acc[r][i]);
                    acc[r][i] = fmaf(a[r].w, b[i].w, acc[r][i]);
                }
        }
        __syncthreads();
    }

    float* S = sm;   // 64 x 132
    #pragma unroll
    for (int r = 0; r < 4; r++)
        #pragma unroll
        for (int i = 0; i < 8; i++) {
            int col = tc + 16*i;
            float bias = (tmode == 0) ? qb[col] : (tmode == 2) ? vb[col] : 0.f;
            S[(tr*4 + r) * 132 + col] = acc[r][i] + bias;
        }
    __syncthreads();
    {
        int row = tid >> 2, hh = tid & 3;
        float f;
        if (tmode == 2) {
            f = 1.f;
        } else {
            const float* p = S + row * 132 + hh * 32;
            float ss = 0.f;
            #pragma unroll
            for (int d = 0; d < 32; d++) ss = fmaf(p[d], p[d], ss);
            f = 1.f / fmaxf(sqrtf(ss), 1e-12f);
            if (tmode == 0) f *= expf(fminf(ls[hh], 4.60517018598809136804f)); // log(100)
        }
        fac[tid] = f;
    }
    __syncthreads();

    float* out = (tmode == 0) ? g_q : (tmode == 1) ? g_k : g_v;
    #pragma unroll
    for (int r = 0; r < 4; r++) {
        int row = tr*4 + r;
        int gr  = r0 + row;
        int b   = gr >> 8, l = gr & 255;
        #pragma unroll
        for (int i = 0; i < 8; i++) {
            int col = tc + 16*i;
            int hh = col >> 5, d = col & 31;
            out[(size_t)(((b * NH + hh) * LQ) + l) * HD + d] = S[row * 132 + col] * fac[row * 4 + hh];
        }
    }
}

// ---------------- flash-style attention per (window, head) ----------------
// 128 threads/CTA; each thread owns TWO query rows (tid, tid+128).
// k/v smem loads per key j are amortized across both rows (halves LDS traffic),
// and all math is packed f32x2 (halves FMA instruction count).
__global__ __launch_bounds__(128, 2) void attn_kernel()
{
    extern __shared__ float sh[];
    float* ks = sh;                 // 256 x 32
    float* vs = sh + LQ * HD;       // 256 x 32
    const int bh = blockIdx.x;      // b*4 + h
    const int h  = bh & 3;
    const int b  = bh >> 2;
    const float* qg = g_q + (size_t)bh * LQ * HD;
    const float* kg = g_k + (size_t)bh * LQ * HD;
    const float* vg = g_v + (size_t)bh * LQ * HD;
    const int tid = threadIdx.x;

    // stage k and v: 2048 float4 each, 128 threads -> 16 reps
    #pragma unroll
    for (int rep = 0; rep < 16; rep++) {
        int f = tid + rep * 128;            // float4 index
        *(float4*)(ks + (size_t)f * 4) = *(const float4*)(kg + (size_t)f * 4);
        *(float4*)(vs + (size_t)f * 4) = *(const float4*)(vg + (size_t)f * 4);
    }
    // two query rows into packed registers (gmem rows are contiguous 32 floats)
    unsigned long long q0p[16], q1p[16];
    {
        const unsigned long long* q0g = (const unsigned long long*)(qg + (size_t)tid * HD);
        const unsigned long long* q1g = (const unsigned long long*)(qg + (size_t)(tid + 128) * HD);
        #pragma unroll
        for (int i = 0; i < 16; i++) { q0p[i] = q0g[i]; q1p[i] = q1g[i]; }
    }
    __syncthreads();

    const float* b0ptr = g_bias + h * (LQ * LQ) + tid * LQ;
    const float* b1ptr = b0ptr + 128 * LQ;

    float m0 = -1e30f, l0 = 0.f, m1 = -1e30f, l1 = 0.f;
    unsigned long long acc0[16], acc1[16];
    #pragma unroll
    for (int i = 0; i < 16; i++) { acc0[i] = 0ull; acc1[i] = 0ull; }

    #pragma unroll 1
    for (int j4 = 0; j4 < LQ / 4; j4++) {
        float4 b0w = *(const float4*)(b0ptr + j4 * 4);
        float4 b1w = *(const float4*)(b1ptr + j4 * 4);
        #pragma unroll
        for (int jj = 0; jj < 4; jj++) {
            int j = j4 * 4 + jj;
            const ulonglong2* krow = (const ulonglong2*)(ks + j * HD);

            unsigned long long sa0 = 0ull, sb0 = 0ull, sa1 = 0ull, sb1 = 0ull;
            #pragma unroll
            for (int i = 0; i < 8; i++) {
                ulonglong2 kk = krow[i];
                sa0 = f2fma(q0p[2*i],   kk.x, sa0);
                sb0 = f2fma(q0p[2*i+1], kk.y, sb0);
                sa1 = f2fma(q1p[2*i],   kk.x, sa1);
                sb1 = f2fma(q1p[2*i+1], kk.y, sb1);
            }
            float x0, y0, x1, y1;
            f2unpack(f2add(sa0, sb0), x0, y0);
            f2unpack(f2add(sa1, sb1), x1, y1);
            float bj0 = (jj == 0) ? b0w.x : (jj == 1) ? b0w.y : (jj == 2) ? b0w.z : b0w.w;
            float bj1 = (jj == 0) ? b1w.x : (jj == 1) ? b1w.y : (jj == 2) ? b1w.z : b1w.w;
            float s0 = x0 + y0 + bj0;
            float s1 = x1 + y1 + bj1;

            // online softmax, row 0
            float mn0 = fmaxf(m0, s0);
            float p0  = __expf(s0 - mn0);
            if (mn0 > m0) {
                float c = __expf(m0 - mn0);
                l0 *= c;
                unsigned long long cc = f2pack(c, c);
                #pragma unroll
                for (int i = 0; i < 16; i++) acc0[i] = f2mul(cc, acc0[i]);
                m0 = mn0;
            }
            l0 += p0;
            // online softmax, row 1
            float mn1 = fmaxf(m1, s1);
            float p1  = __expf(s1 - mn1);
            if (mn1 > m1) {
                float c = __expf(m1 - mn1);
                l1 *= c;
                unsigned long long cc = f2pack(c, c);
                #pragma unroll
                for (int i = 0; i < 16; i++) acc1[i] = f2mul(cc, acc1[i]);
                m1 = mn1;
            }
            l1 += p1;

            unsigned long long pp0 = f2pack(p0, p0);
            unsigned long long pp1 = f2pack(p1, p1);
            const ulonglong2* vrow = (const ulonglong2*)(vs + j * HD);
            #pragma unroll
            for (int i = 0; i < 8; i++) {
                ulonglong2 vv = vrow[i];
                acc0[2*i]   = f2fma(pp0, vv.x, acc0[2*i]);
                acc0[2*i+1] = f2fma(pp0, vv.y, acc0[2*i+1]);
                acc1[2*i]   = f2fma(pp1, vv.x, acc1[2*i]);
                acc1[2*i+1] = f2fma(pp1, vv.y, acc1[2*i+1]);
            }
        }
    }

    unsigned long long inv0 = f2pack(1.f / l0, 1.f / l0);
    unsigned long long inv1 = f2pack(1.f / l1, 1.f / l1);
    unsigned long long* op0 = (unsigned long long*)(g_att + ((size_t)(b * LQ + tid)) * CD + h * HD);
    unsigned long long* op1 = (unsigned long long*)(g_att + ((size_t)(b * LQ + tid + 128)) * CD + h * HD);
    #pragma unroll
    for (int i = 0; i < 16; i++) {
        op0[i] = f2mul(inv0, acc0[i]);
        op1[i] = f2mul(inv1, acc1[i]);
    }
}

// ---------------- projection GEMM: out = att @ proj_w^T + proj_b ----------------
__global__ __launch_bounds__(256) void proj_gemm_kernel(
    const float* __restrict__ W,     // proj_w (128,128)
    const float* __restrict__ pb,    // (128,)
    float* __restrict__ out)
{
    __shared__ float sm[64*36 + 128*36];
    float* As = sm;
    float* Ws = sm + 64*36;
    const int tid = threadIdx.x;
    const int r0 = blockIdx.x * 64;
    const int tr = tid >> 4, tc = tid & 15;
    const float* A = g_att;

    float acc[4][8];
    #pragma unroll
    for (int r = 0; r < 4; r++)
        #pragma unroll
        for (int i = 0; i < 8; i++) acc[r][i] = 0.f;

    for (int kc = 0; kc < 4; kc++) {
        const int k0 = kc * 32;
        {
            int f = tid;
            #pragma unroll
            for (int rep = 0; rep < 2; rep++, f += 256) {
                int row = f >> 3, c4 = f & 7;
                float4 v = *(const float4*)(A + (size_t)(r0 + row) * CD + k0 + c4 * 4);
                float* d = As + row * 36 + c4 * 4;
                d[0] = v.x; d[1] = v.y; d[2] = v.z; d[3] = v.w;
            }
        }
        {
            int f = tid;
            #pragma unroll
            for (int rep = 0; rep < 4; rep++, f += 256) {
                int row = f >> 3, c4 = f & 7;
                float4 v = *(const float4*)(W + row * CD + k0 + c4 * 4);
                float* d = Ws + row * 36 + c4 * 4;
                d[0] = v.x; d[1] = v.y; d[2] = v.z; d[3] = v.w;
            }
        }
        __syncthreads();
        #pragma unroll
        for (int k4 = 0; k4 < 8; k4++) {
            float4 a[4], b[8];
            #pragma unroll
            for (int r = 0; r < 4; r++) a[r] = *(const float4*)(As + (tr*4 + r) * 36 + k4 * 4);
            #pragma unroll
            for (int i = 0; i < 8; i++) b[i] = *(const float4*)(Ws + (tc + 16*i) * 36 + k4 * 4);
            #pragma unroll
            for (int r = 0; r < 4; r++)
                #pragma unroll
                for (int i = 0; i < 8; i++) {
                    acc[r][i] = fmaf(a[r].x, b[i].x, acc[r][i]);
                    acc[r][i] = fmaf(a[r].y, b[i].y, acc[r][i]);
                    acc[r][i] = fmaf(a[r].z, b[i].z, acc[r][i]);
                    acc[r][i] = fmaf(a[r].w, b[i].w, acc[r][i]);
                }
        }
        __syncthreads();
    }

    #pragma unroll
    for (int r = 0; r < 4; r++) {
        int gr = r0 + tr*4 + r;
        #pragma unroll
        for (int i = 0; i < 8; i++) {
            int col = tc + 16*i;
            out[(size_t)gr * CD + col] = acc[r][i] + pb[col];
        }
    }
}

// ---------------- launch ----------------
extern "C" void kernel_launch(void* const* d_in, const int* in_sizes, int n_in,
                              void* d_out, int out_size)
{
    (void)in_sizes; (void)n_in; (void)out_size;
    const float* x       = (const float*)d_in[0];
    const float* qkv_w   = (const float*)d_in[1];
    const float* q_bias  = (const float*)d_in[2];
    const float* v_bias  = (const float*)d_in[3];
    const float* lscale  = (const float*)d_in[4];
    const float* cpb_w1  = (const float*)d_in[5];
    const float* cpb_b1  = (const float*)d_in[6];
    const float* cpb_w2  = (const float*)d_in[7];
    const float* proj_w  = (const float*)d_in[8];
    const float* proj_b  = (const float*)d_in[9];
    const float* rtable  = (const float*)d_in[10];
    const int*   ridx    = (const int*)d_in[11];
    float* out = (float*)d_out;

    static const int attn_smem = 2 * LQ * HD * 4;   // 65536 bytes
    cudaFuncSetAttribute(attn_kernel, cudaFuncAttributeMaxDynamicSharedMemorySize, attn_smem);

    cpb_kernel<<<(MT + 31) / 32, 256>>>(rtable, cpb_w1, cpb_b1, cpb_w2);
    bias_gather_kernel<<<(NH * LQ * LQ) / 256, 256>>>(ridx);
    qkv_gemm_kernel<<<dim3((NW * LQ) / 64, 3), 256>>>(x, qkv_w, q_bias, v_bias, lscale);
    attn_kernel<<<NW * NH, 256 / 2, attn_smem>>>();
    proj_gemm_kernel<<<(NW * LQ) / 64, 256>>>(proj_w, proj_b, out);
}

// round 5
// speedup vs baseline: 1.2785x; 1.0572x over previous
#include <cuda_runtime.h>
#include <math.h>

#define NW 512      // num windows (B_)
#define LQ 256      // tokens per window (L)
#define CD 128      // channels (C)
#define NH 4        // heads
#define HD 32       // head dim
#define MT 1575     // rel table rows (15*15*7)

// ---------------- packed f32x2 helpers (Blackwell PTX-only ops) ----------------
__device__ __forceinline__ unsigned long long f2pack(float lo, float hi) {
    unsigned long long r;
    asm("mov.b64 %0, {%1, %2};" : "=l"(r) : "f"(lo), "f"(hi));
    return r;
}
__device__ __forceinline__ void f2unpack(unsigned long long v, float& lo, float& hi) {
    asm("mov.b64 {%0, %1}, %2;" : "=f"(lo), "=f"(hi) : "l"(v));
}
__device__ __forceinline__ unsigned long long f2fma(unsigned long long a,
                                                    unsigned long long b,
                                                    unsigned long long c) {
    unsigned long long d;
    asm("fma.rn.f32x2 %0, %1, %2, %3;" : "=l"(d) : "l"(a), "l"(b), "l"(c));
    return d;
}
__device__ __forceinline__ unsigned long long f2add(unsigned long long a,
                                                    unsigned long long b) {
    unsigned long long d;
    asm("add.rn.f32x2 %0, %1, %2;" : "=l"(d) : "l"(a), "l"(b));
    return d;
}
__device__ __forceinline__ unsigned long long f2mul(unsigned long long a,
                                                    unsigned long long b) {
    unsigned long long d;
    asm("mul.rn.f32x2 %0, %1, %2;" : "=l"(d) : "l"(a), "l"(b));
    return d;
}

// ---------------- device scratch (no runtime allocation allowed) ----------------
static __device__ float g_bias_table[MT * NH];                    // (M, H)
static __device__ float g_bias[NH * LQ * LQ];                     // 16*sigmoid, (H, L, L)
static __device__ float g_q[(size_t)NW * NH * LQ * HD];           // normalized+scaled q
static __device__ float g_k[(size_t)NW * NH * LQ * HD];           // normalized k
static __device__ float g_v[(size_t)NW * NH * LQ * HD];           // v
static __device__ float g_att[(size_t)NW * LQ * CD];              // attention output (B,L,C)

// ---------------- CPB MLP ----------------
__global__ void cpb_kernel(const float* __restrict__ table, const float* __restrict__ w1,
                           const float* __restrict__ b1, const float* __restrict__ w2)
{
    int t  = threadIdx.x;
    int mi = t >> 3, ui = t & 7;
    int m  = blockIdx.x * 32 + mi;
    float a0 = 0.f, a1 = 0.f, a2 = 0.f, a3 = 0.f;
    if (m < MT) {
        float t0 = table[m*3+0], t1 = table[m*3+1], t2 = table[m*3+2];
        for (int u = ui; u < 512; u += 8) {
            float hid = fmaf(w1[u*3+0], t0, fmaf(w1[u*3+1], t1, fmaf(w1[u*3+2], t2, b1[u])));
            hid = fmaxf(hid, 0.f);
            a0 = fmaf(hid, w2[u],        a0);
            a1 = fmaf(hid, w2[512+u],    a1);
            a2 = fmaf(hid, w2[1024+u],   a2);
            a3 = fmaf(hid, w2[1536+u],   a3);
        }
    }
    #pragma unroll
    for (int off = 4; off >= 1; off >>= 1) {
        a0 += __shfl_down_sync(0xffffffffu, a0, off, 8);
        a1 += __shfl_down_sync(0xffffffffu, a1, off, 8);
        a2 += __shfl_down_sync(0xffffffffu, a2, off, 8);
        a3 += __shfl_down_sync(0xffffffffu, a3, off, 8);
    }
    if (ui == 0 && m < MT) {
        g_bias_table[m*NH+0] = a0;
        g_bias_table[m*NH+1] = a1;
        g_bias_table[m*NH+2] = a2;
        g_bias_table[m*NH+3] = a3;
    }
}

// ---------------- bias gather + 16*sigmoid ----------------
__global__ void bias_gather_kernel(const int* __restrict__ idx)
{
    int i = blockIdx.x * blockDim.x + threadIdx.x;   // over NH*LQ*LQ = 262144
    if (i >= NH * LQ * LQ) return;
    int h  = i >> 16;
    int ij = i & 65535;
    float x = g_bias_table[idx[ij] * NH + h];
    g_bias[i] = 16.f / (1.f + __expf(-x));
}

// ---------------- QKV GEMM (64x128 tile) + fused bias/normalize, f32x2 math ------
__global__ __launch_bounds__(256, 2) void qkv_gemm_kernel(
    const float* __restrict__ A,      // x flattened (131072, 128)
    const float* __restrict__ W,      // qkv_w (384, 128)
    const float* __restrict__ qb,     // (128,)
    const float* __restrict__ vb,     // (128,)
    const float* __restrict__ ls)     // logit_scale (4,)
{
    __shared__ float sm[8448];
    __shared__ float fac[64 * 4];
    float* As = sm;                   // 64 x 36
    float* Ws = sm + 64*36;           // 128 x 36
    const int tid = threadIdx.x;
    const int tmode = blockIdx.y;     // 0 q, 1 k, 2 v
    const int r0 = blockIdx.x * 64;
    const int tr = tid >> 4, tc = tid & 15;

    // packed accumulators: lane .x/.y hold even/odd-k partial sums
    unsigned long long acc2[4][8];
    #pragma unroll
    for (int r = 0; r < 4; r++)
        #pragma unroll
        for (int i = 0; i < 8; i++) acc2[r][i] = 0ull;

    const float* Wbase = W + tmode * 128 * 128;

    for (int kc = 0; kc < 4; kc++) {
        const int k0 = kc * 32;
        {
            int f = tid;
            #pragma unroll
            for (int rep = 0; rep < 2; rep++, f += 256) {
                int row = f >> 3, c4 = f & 7;
                float4 v = *(const float4*)(A + (size_t)(r0 + row) * CD + k0 + c4 * 4);
                float* d = As + row * 36 + c4 * 4;
                d[0] = v.x; d[1] = v.y; d[2] = v.z; d[3] = v.w;
            }
        }
        {
            int f = tid;
            #pragma unroll
            for (int rep = 0; rep < 4; rep++, f += 256) {
                int row = f >> 3, c4 = f & 7;
                float4 v = *(const float4*)(Wbase + row * CD + k0 + c4 * 4);
                float* d = Ws + row * 36 + c4 * 4;
                d[0] = v.x; d[1] = v.y; d[2] = v.z; d[3] = v.w;
            }
        }
        __syncthreads();
        #pragma unroll
        for (int k4 = 0; k4 < 8; k4++) {
            ulonglong2 a2[4], b2[8];
            #pragma unroll
            for (int r = 0; r < 4; r++)
                a2[r] = *(const ulonglong2*)(As + (tr*4 + r) * 36 + k4 * 4);
            #pragma unroll
            for (int i = 0; i < 8; i++)
                b2[i] = *(const ulonglong2*)(Ws + (tc + 16*i) * 36 + k4 * 4);
            #pragma unroll
            for (int r = 0; r < 4; r++)
                #pragma unroll
                for (int i = 0; i < 8; i++) {
                    acc2[r][i] = f2fma(a2[r].x, b2[i].x, acc2[r][i]);
                    acc2[r][i] = f2fma(a2[r].y, b2[i].y, acc2[r][i]);
                }
        }
        __syncthreads();
    }

    float acc[4][8];
    #pragma unroll
    for (int r = 0; r < 4; r++)
        #pragma unroll
        for (int i = 0; i < 8; i++) {
            float lo, hi;
            f2unpack(acc2[r][i], lo, hi);
            acc[r][i] = lo + hi;
        }

    float* S = sm;   // 64 x 132
    #pragma unroll
    for (int r = 0; r < 4; r++)
        #pragma unroll
        for (int i = 0; i < 8; i++) {
            int col = tc + 16*i;
            float bias = (tmode == 0) ? qb[col] : (tmode == 2) ? vb[col] : 0.f;
            S[(tr*4 + r) * 132 + col] = acc[r][i] + bias;
        }
    __syncthreads();
    {
        int row = tid >> 2, hh = tid & 3;
        float f;
        if (tmode == 2) {
            f = 1.f;
        } else {
            const float* p = S + row * 132 + hh * 32;
            float ss = 0.f;
            #pragma unroll
            for (int d = 0; d < 32; d++) ss = fmaf(p[d], p[d], ss);
            f = 1.f / fmaxf(sqrtf(ss), 1e-12f);
            if (tmode == 0) f *= expf(fminf(ls[hh], 4.60517018598809136804f)); // log(100)
        }
        fac[tid] = f;
    }
    __syncthreads();

    float* out = (tmode == 0) ? g_q : (tmode == 1) ? g_k : g_v;
    #pragma unroll
    for (int r = 0; r < 4; r++) {
        int row = tr*4 + r;
        int gr  = r0 + row;
        int b   = gr >> 8, l = gr & 255;
        #pragma unroll
        for (int i = 0; i < 8; i++) {
            int col = tc + 16*i;
            int hh = col >> 5, d = col & 31;
            out[(size_t)(((b * NH + hh) * LQ) + l) * HD + d] = S[row * 132 + col] * fac[row * 4 + hh];
        }
    }
}

// ---------------- flash-style attention per (window, head) ----------------
// 128 threads/CTA; each thread owns TWO query rows (tid, tid+128).
// Register cap for 3 CTAs/SM (<=170 regs) to raise occupancy/issue rate.
__global__ __launch_bounds__(128, 3) void attn_kernel()
{
    extern __shared__ float sh[];
    float* ks = sh;                 // 256 x 32
    float* vs = sh + LQ * HD;       // 256 x 32
    const int bh = blockIdx.x;      // b*4 + h
    const int h  = bh & 3;
    const int b  = bh >> 2;
    const float* qg = g_q + (size_t)bh * LQ * HD;
    const float* kg = g_k + (size_t)bh * LQ * HD;
    const float* vg = g_v + (size_t)bh * LQ * HD;
    const int tid = threadIdx.x;

    // stage k and v: 2048 float4 each, 128 threads -> 16 reps
    #pragma unroll
    for (int rep = 0; rep < 16; rep++) {
        int f = tid + rep * 128;            // float4 index
        *(float4*)(ks + (size_t)f * 4) = *(const float4*)(kg + (size_t)f * 4);
        *(float4*)(vs + (size_t)f * 4) = *(const float4*)(vg + (size_t)f * 4);
    }
    // two query rows into packed registers
    unsigned long long q0p[16], q1p[16];
    {
        const unsigned long long* q0g = (const unsigned long long*)(qg + (size_t)tid * HD);
        const unsigned long long* q1g = (const unsigned long long*)(qg + (size_t)(tid + 128) * HD);
        #pragma unroll
        for (int i = 0; i < 16; i++) { q0p[i] = q0g[i]; q1p[i] = q1g[i]; }
    }
    __syncthreads();

    const float* b0ptr = g_bias + h * (LQ * LQ) + tid * LQ;
    const float* b1ptr = b0ptr + 128 * LQ;

    float m0 = -1e30f, l0 = 0.f, m1 = -1e30f, l1 = 0.f;
    unsigned long long acc0[16], acc1[16];
    #pragma unroll
    for (int i = 0; i < 16; i++) { acc0[i] = 0ull; acc1[i] = 0ull; }

    #pragma unroll 1
    for (int j4 = 0; j4 < LQ / 4; j4++) {
        float4 b0w = *(const float4*)(b0ptr + j4 * 4);
        float4 b1w = *(const float4*)(b1ptr + j4 * 4);
        #pragma unroll
        for (int jj = 0; jj < 4; jj++) {
            int j = j4 * 4 + jj;
            const ulonglong2* krow = (const ulonglong2*)(ks + j * HD);

            unsigned long long sa0 = 0ull, sb0 = 0ull, sa1 = 0ull, sb1 = 0ull;
            #pragma unroll
            for (int i = 0; i < 8; i++) {
                ulonglong2 kk = krow[i];
                sa0 = f2fma(q0p[2*i],   kk.x, sa0);
                sb0 = f2fma(q0p[2*i+1], kk.y, sb0);
                sa1 = f2fma(q1p[2*i],   kk.x, sa1);
                sb1 = f2fma(q1p[2*i+1], kk.y, sb1);
            }
            float x0, y0, x1, y1;
            f2unpack(f2add(sa0, sb0), x0, y0);
            f2unpack(f2add(sa1, sb1), x1, y1);
            float bj0 = (jj == 0) ? b0w.x : (jj == 1) ? b0w.y : (jj == 2) ? b0w.z : b0w.w;
            float bj1 = (jj == 0) ? b1w.x : (jj == 1) ? b1w.y : (jj == 2) ? b1w.z : b1w.w;
            float s0 = x0 + y0 + bj0;
            float s1 = x1 + y1 + bj1;

            // online softmax, row 0
            float mn0 = fmaxf(m0, s0);
            float p0  = __expf(s0 - mn0);
            if (mn0 > m0) {
                float c = __expf(m0 - mn0);
                l0 *= c;
                unsigned long long cc = f2pack(c, c);
                #pragma unroll
                for (int i = 0; i < 16; i++) acc0[i] = f2mul(cc, acc0[i]);
                m0 = mn0;
            }
            l0 += p0;
            // online softmax, row 1
            float mn1 = fmaxf(m1, s1);
            float p1  = __expf(s1 - mn1);
            if (mn1 > m1) {
                float c = __expf(m1 - mn1);
                l1 *= c;
                unsigned long long cc = f2pack(c, c);
                #pragma unroll
                for (int i = 0; i < 16; i++) acc1[i] = f2mul(cc, acc1[i]);
                m1 = mn1;
            }
            l1 += p1;

            unsigned long long pp0 = f2pack(p0, p0);
            unsigned long long pp1 = f2pack(p1, p1);
            const ulonglong2* vrow = (const ulonglong2*)(vs + j * HD);
            #pragma unroll
            for (int i = 0; i < 8; i++) {
                ulonglong2 vv = vrow[i];
                acc0[2*i]   = f2fma(pp0, vv.x, acc0[2*i]);
                acc0[2*i+1] = f2fma(pp0, vv.y, acc0[2*i+1]);
                acc1[2*i]   = f2fma(pp1, vv.x, acc1[2*i]);
                acc1[2*i+1] = f2fma(pp1, vv.y, acc1[2*i+1]);
            }
        }
    }

    unsigned long long inv0 = f2pack(1.f / l0, 1.f / l0);
    unsigned long long inv1 = f2pack(1.f / l1, 1.f / l1);
    unsigned long long* op0 = (unsigned long long*)(g_att + ((size_t)(b * LQ + tid)) * CD + h * HD);
    unsigned long long* op1 = (unsigned long long*)(g_att + ((size_t)(b * LQ + tid + 128)) * CD + h * HD);
    #pragma unroll
    for (int i = 0; i < 16; i++) {
        op0[i] = f2mul(inv0, acc0[i]);
        op1[i] = f2mul(inv1, acc1[i]);
    }
}

// ---------------- projection GEMM: out = att @ proj_w^T + proj_b, f32x2 math ------
__global__ __launch_bounds__(256, 2) void proj_gemm_kernel(
    const float* __restrict__ W,     // proj_w (128,128)
    const float* __restrict__ pb,    // (128,)
    float* __restrict__ out)
{
    __shared__ float sm[64*36 + 128*36];
    float* As = sm;
    float* Ws = sm + 64*36;
    const int tid = threadIdx.x;
    const int r0 = blockIdx.x * 64;
    const int tr = tid >> 4, tc = tid & 15;
    const float* A = g_att;

    unsigned long long acc2[4][8];
    #pragma unroll
    for (int r = 0; r < 4; r++)
        #pragma unroll
        for (int i = 0; i < 8; i++) acc2[r][i] = 0ull;

    for (int kc = 0; kc < 4; kc++) {
        const int k0 = kc * 32;
        {
            int f = tid;
            #pragma unroll
            for (int rep = 0; rep < 2; rep++, f += 256) {
                int row = f >> 3, c4 = f & 7;
                float4 v = *(const float4*)(A + (size_t)(r0 + row) * CD + k0 + c4 * 4);
                float* d = As + row * 36 + c4 * 4;
                d[0] = v.x; d[1] = v.y; d[2] = v.z; d[3] = v.w;
            }
        }
        {
            int f = tid;
            #pragma unroll
            for (int rep = 0; rep < 4; rep++, f += 256) {
                int row = f >> 3, c4 = f & 7;
                float4 v = *(const float4*)(W + row * CD + k0 + c4 * 4);
                float* d = Ws + row * 36 + c4 * 4;
                d[0] = v.x; d[1] = v.y; d[2] = v.z; d[3] = v.w;
            }
        }
        __syncthreads();
        #pragma unroll
        for (int k4 = 0; k4 < 8; k4++) {
            ulonglong2 a2[4], b2[8];
            #pragma unroll
            for (int r = 0; r < 4; r++)
                a2[r] = *(const ulonglong2*)(As + (tr*4 + r) * 36 + k4 * 4);
            #pragma unroll
            for (int i = 0; i < 8; i++)
                b2[i] = *(const ulonglong2*)(Ws + (tc + 16*i) * 36 + k4 * 4);
            #pragma unroll
            for (int r = 0; r < 4; r++)
                #pragma unroll
                for (int i = 0; i < 8; i++) {
                    acc2[r][i] = f2fma(a2[r].x, b2[i].x, acc2[r][i]);
                    acc2[r][i] = f2fma(a2[r].y, b2[i].y, acc2[r][i]);
                }
        }
        __syncthreads();
    }

    #pragma unroll
    for (int r = 0; r < 4; r++) {
        int gr = r0 + tr*4 + r;
        #pragma unroll
        for (int i = 0; i < 8; i++) {
            int col = tc + 16*i;
            float lo, hi;
            f2unpack(acc2[r][i], lo, hi);
            out[(size_t)gr * CD + col] = lo + hi + pb[col];
        }
    }
}

// ---------------- launch ----------------
extern "C" void kernel_launch(void* const* d_in, const int* in_sizes, int n_in,
                              void* d_out, int out_size)
{
    (void)in_sizes; (void)n_in; (void)out_size;
    const float* x       = (const float*)d_in[0];
    const float* qkv_w   = (const float*)d_in[1];
    const float* q_bias  = (const float*)d_in[2];
    const float* v_bias  = (const float*)d_in[3];
    const float* lscale  = (const float*)d_in[4];
    const float* cpb_w1  = (const float*)d_in[5];
    const float* cpb_b1  = (const float*)d_in[6];
    const float* cpb_w2  = (const float*)d_in[7];
    const float* proj_w  = (const float*)d_in[8];
    const float* proj_b  = (const float*)d_in[9];
    const float* rtable  = (const float*)d_in[10];
    const int*   ridx    = (const int*)d_in[11];
    float* out = (float*)d_out;

    static const int attn_smem = 2 * LQ * HD * 4;   // 65536 bytes
    cudaFuncSetAttribute(attn_kernel, cudaFuncAttributeMaxDynamicSharedMemorySize, attn_smem);

    cpb_kernel<<<(MT + 31) / 32, 256>>>(rtable, cpb_w1, cpb_b1, cpb_w2);
    bias_gather_kernel<<<(NH * LQ * LQ) / 256, 256>>>(ridx);
    qkv_gemm_kernel<<<dim3((NW * LQ) / 64, 3), 256>>>(x, qkv_w, q_bias, v_bias, lscale);
    attn_kernel<<<NW * NH, 128, attn_smem>>>();
    proj_gemm_kernel<<<(NW * LQ) / 64, 256>>>(proj_w, proj_b, out);
}

// round 7
// speedup vs baseline: 1.3368x; 1.0456x over previous
#include <cuda_runtime.h>
#include <math.h>

#define NW 512      // num windows (B_)
#define LQ 256      // tokens per window (L)
#define CD 128      // channels (C)
#define NH 4        // heads
#define HD 32       // head dim
#define MT 1575     // rel table rows (15*15*7)

// ---------------- packed f32x2 helpers (Blackwell PTX-only ops) ----------------
__device__ __forceinline__ unsigned long long f2pack(float lo, float hi) {
    unsigned long long r;
    asm("mov.b64 %0, {%1, %2};" : "=l"(r) : "f"(lo), "f"(hi));
    return r;
}
__device__ __forceinline__ void f2unpack(unsigned long long v, float& lo, float& hi) {
    asm("mov.b64 {%0, %1}, %2;" : "=f"(lo), "=f"(hi) : "l"(v));
}
__device__ __forceinline__ unsigned long long f2fma(unsigned long long a,
                                                    unsigned long long b,
                                                    unsigned long long c) {
    unsigned long long d;
    asm("fma.rn.f32x2 %0, %1, %2, %3;" : "=l"(d) : "l"(a), "l"(b), "l"(c));
    return d;
}
__device__ __forceinline__ unsigned long long f2add(unsigned long long a,
                                                    unsigned long long b) {
    unsigned long long d;
    asm("add.rn.f32x2 %0, %1, %2;" : "=l"(d) : "l"(a), "l"(b));
    return d;
}
__device__ __forceinline__ unsigned long long f2mul(unsigned long long a,
                                                    unsigned long long b) {
    unsigned long long d;
    asm("mul.rn.f32x2 %0, %1, %2;" : "=l"(d) : "l"(a), "l"(b));
    return d;
}

// ---------------- device scratch (no runtime allocation allowed) ----------------
static __device__ float g_bias_table[MT * NH];                    // (M, H)
static __device__ float g_bias[NH * LQ * LQ];                     // 16*sigmoid - M_h, (H,L,L)
static __device__ float g_q[(size_t)NW * NH * LQ * HD];           // normalized+scaled q
static __device__ float g_k[(size_t)NW * NH * LQ * HD];           // normalized k
static __device__ float g_v[(size_t)NW * NH * LQ * HD];           // v
static __device__ float g_att[(size_t)NW * LQ * CD];              // attention output (B,L,C)

// ---------------- CPB MLP ----------------
__global__ void cpb_kernel(const float* __restrict__ table, const float* __restrict__ w1,
                           const float* __restrict__ b1, const float* __restrict__ w2)
{
    int t  = threadIdx.x;
    int mi = t >> 3, ui = t & 7;
    int m  = blockIdx.x * 32 + mi;
    float a0 = 0.f, a1 = 0.f, a2 = 0.f, a3 = 0.f;
    if (m < MT) {
        float t0 = table[m*3+0], t1 = table[m*3+1], t2 = table[m*3+2];
        for (int u = ui; u < 512; u += 8) {
            float hid = fmaf(w1[u*3+0], t0, fmaf(w1[u*3+1], t1, fmaf(w1[u*3+2], t2, b1[u])));
            hid = fmaxf(hid, 0.f);
            a0 = fmaf(hid, w2[u],        a0);
            a1 = fmaf(hid, w2[512+u],    a1);
            a2 = fmaf(hid, w2[1024+u],   a2);
            a3 = fmaf(hid, w2[1536+u],   a3);
        }
    }
    #pragma unroll
    for (int off = 4; off >= 1; off >>= 1) {
        a0 += __shfl_down_sync(0xffffffffu, a0, off, 8);
        a1 += __shfl_down_sync(0xffffffffu, a1, off, 8);
        a2 += __shfl_down_sync(0xffffffffu, a2, off, 8);
        a3 += __shfl_down_sync(0xffffffffu, a3, off, 8);
    }
    if (ui == 0 && m < MT) {
        g_bias_table[m*NH+0] = a0;
        g_bias_table[m*NH+1] = a1;
        g_bias_table[m*NH+2] = a2;
        g_bias_table[m*NH+3] = a3;
    }
}

// ---------------- bias gather + 16*sigmoid - M_h ----------------
// Folds the per-head logit upper bound M_h = scale_h + 16 into the bias table
// so attention needs NO online max: s' = q.k + bias' <= 0, and the diagonal
// term (q_i.k_i = scale_h exactly, since q,k normalize the same vector) keeps
// the softmax denominator >= exp(-16): division is always safe, and any terms
// that underflow to 0 are correctly negligible.
__global__ void bias_gather_kernel(const int* __restrict__ idx, const float* __restrict__ ls)
{
    int i = blockIdx.x * blockDim.x + threadIdx.x;   // over NH*LQ*LQ = 262144
    if (i >= NH * LQ * LQ) return;
    int h  = i >> 16;
    int ij = i & 65535;
    float mh = expf(fminf(ls[h], 4.60517018598809136804f)) + 16.f;  // scale_h + 16
    float x = g_bias_table[idx[ij] * NH + h];
    g_bias[i] = 16.f / (1.f + __expf(-x)) - mh;
}

// ---------------- QKV GEMM (64x128 tile) + fused bias/normalize, f32x2 math ------
__global__ __launch_bounds__(256, 2) void qkv_gemm_kernel(
    const float* __restrict__ A,      // x flattened (131072, 128)
    const float* __restrict__ W,      // qkv_w (384, 128)
    const float* __restrict__ qb,     // (128,)
    const float* __restrict__ vb,     // (128,)
    const float* __restrict__ ls)     // logit_scale (4,)
{
    __shared__ float sm[8448];
    __shared__ float fac[64 * 4];
    float* As = sm;                   // 64 x 36
    float* Ws = sm + 64*36;           // 128 x 36
    const int tid = threadIdx.x;
    const int tmode = blockIdx.y;     // 0 q, 1 k, 2 v
    const int r0 = blockIdx.x * 64;
    const int tr = tid >> 4, tc = tid & 15;

    unsigned long long acc2[4][8];
    #pragma unroll
    for (int r = 0; r < 4; r++)
        #pragma unroll
        for (int i = 0; i < 8; i++) acc2[r][i] = 0ull;

    const float* Wbase = W + tmode * 128 * 128;

    for (int kc = 0; kc < 4; kc++) {
        const int k0 = kc * 32;
        {
            int f = tid;
            #pragma unroll
            for (int rep = 0; rep < 2; rep++, f += 256) {
                int row = f >> 3, c4 = f & 7;
                float4 v = *(const float4*)(A + (size_t)(r0 + row) * CD + k0 + c4 * 4);
                float* d = As + row * 36 + c4 * 4;
                d[0] = v.x; d[1] = v.y; d[2] = v.z; d[3] = v.w;
            }
        }
        {
            int f = tid;
            #pragma unroll
            for (int rep = 0; rep < 4; rep++, f += 256) {
                int row = f >> 3, c4 = f & 7;
                float4 v = *(const float4*)(Wbase + row * CD + k0 + c4 * 4);
                float* d = Ws + row * 36 + c4 * 4;
                d[0] = v.x; d[1] = v.y; d[2] = v.z; d[3] = v.w;
            }
        }
        __syncthreads();
        #pragma unroll
        for (int k4 = 0; k4 < 8; k4++) {
            ulonglong2 a2[4], b2[8];
            #pragma unroll
            for (int r = 0; r < 4; r++)
                a2[r] = *(const ulonglong2*)(As + (tr*4 + r) * 36 + k4 * 4);
            #pragma unroll
            for (int i = 0; i < 8; i++)
                b2[i] = *(const ulonglong2*)(Ws + (tc + 16*i) * 36 + k4 * 4);
            #pragma unroll
            for (int r = 0; r < 4; r++)
                #pragma unroll
                for (int i = 0; i < 8; i++) {
                    acc2[r][i] = f2fma(a2[r].x, b2[i].x, acc2[r][i]);
                    acc2[r][i] = f2fma(a2[r].y, b2[i].y, acc2[r][i]);
                }
        }
        __syncthreads();
    }

    float acc[4][8];
    #pragma unroll
    for (int r = 0; r < 4; r++)
        #pragma unroll
        for (int i = 0; i < 8; i++) {
            float lo, hi;
            f2unpack(acc2[r][i], lo, hi);
            acc[r][i] = lo + hi;
        }

    float* S = sm;   // 64 x 132
    #pragma unroll
    for (int r = 0; r < 4; r++)
        #pragma unroll
        for (int i = 0; i < 8; i++) {
            int col = tc + 16*i;
            float bias = (tmode == 0) ? qb[col] : (tmode == 2) ? vb[col] : 0.f;
            S[(tr*4 + r) * 132 + col] = acc[r][i] + bias;
        }
    __syncthreads();
    {
        int row = tid >> 2, hh = tid & 3;
        float f;
        if (tmode == 2) {
            f = 1.f;
        } else {
            const float* p = S + row * 132 + hh * 32;
            float ss = 0.f;
            #pragma unroll
            for (int d = 0; d < 32; d++) ss = fmaf(p[d], p[d], ss);
            f = 1.f / fmaxf(sqrtf(ss), 1e-12f);
            if (tmode == 0) f *= expf(fminf(ls[hh], 4.60517018598809136804f)); // log(100)
        }
        fac[tid] = f;
    }
    __syncthreads();

    float* out = (tmode == 0) ? g_q : (tmode == 1) ? g_k : g_v;
    #pragma unroll
    for (int r = 0; r < 4; r++) {
        int row = tr*4 + r;
        int gr  = r0 + row;
        int b   = gr >> 8, l = gr & 255;
        #pragma unroll
        for (int i = 0; i < 8; i++) {
            int col = tc + 16*i;
            int hh = col >> 5, d = col & 31;
            out[(size_t)(((b * NH + hh) * LQ) + l) * HD + d] = S[row * 132 + col] * fac[row * 4 + hh];
        }
    }
}

// ---------------- flash-style attention per (window, head) ----------------
// 128 threads/CTA; each thread owns TWO query rows (tid, tid+128).
// BRANCH-FREE softmax: the bias table already has the per-head logit upper
// bound folded in, so s' <= 0 and exp(s') never overflows; underflow-to-zero
// terms are correctly negligible because the diagonal keeps l >= exp(-16).
__global__ __launch_bounds__(128, 3) void attn_kernel()
{
    extern __shared__ float sh[];
    float* ks = sh;                 // 256 x 32
    float* vs = sh + LQ * HD;       // 256 x 32
    const int bh = blockIdx.x;      // b*4 + h
    const int h  = bh & 3;
    const int b  = bh >> 2;
    const float* qg = g_q + (size_t)bh * LQ * HD;
    const float* kg = g_k + (size_t)bh * LQ * HD;
    const float* vg = g_v + (size_t)bh * LQ * HD;
    const int tid = threadIdx.x;

    // stage k and v: 2048 float4 each, 128 threads -> 16 reps
    #pragma unroll
    for (int rep = 0; rep < 16; rep++) {
        int f = tid + rep * 128;            // float4 index
        *(float4*)(ks + (size_t)f * 4) = *(const float4*)(kg + (size_t)f * 4);
        *(float4*)(vs + (size_t)f * 4) = *(const float4*)(vg + (size_t)f * 4);
    }
    // two query rows into packed registers
    unsigned long long q0p[16], q1p[16];
    {
        const unsigned long long* q0g = (const unsigned long long*)(qg + (size_t)tid * HD);
        const unsigned long long* q1g = (const unsigned long long*)(qg + (size_t)(tid + 128) * HD);
        #pragma unroll
        for (int i = 0; i < 16; i++) { q0p[i] = q0g[i]; q1p[i] = q1g[i]; }
    }
    __syncthreads();

    const float* b0ptr = g_bias + h * (LQ * LQ) + tid * LQ;
    const float* b1ptr = b0ptr + 128 * LQ;

    float l0 = 0.f, l1 = 0.f;
    unsigned long long acc0[16], acc1[16];
    #pragma unroll
    for (int i = 0; i < 16; i++) { acc0[i] = 0ull; acc1[i] = 0ull; }

    #pragma unroll 1
    for (int j4 = 0; j4 < LQ / 4; j4++) {
        float4 b0w = *(const float4*)(b0ptr + j4 * 4);
        float4 b1w = *(const float4*)(b1ptr + j4 * 4);
        #pragma unroll
        for (int jj = 0; jj < 4; jj++) {
            int j = j4 * 4 + jj;
            const ulonglong2* krow = (const ulonglong2*)(ks + j * HD);

            unsigned long long sa0 = 0ull, sb0 = 0ull, sa1 = 0ull, sb1 = 0ull;
            #pragma unroll
            for (int i = 0; i < 8; i++) {
                ulonglong2 kk = krow[i];
                sa0 = f2fma(q0p[2*i],   kk.x, sa0);
                sb0 = f2fma(q0p[2*i+1], kk.y, sb0);
                sa1 = f2fma(q1p[2*i],   kk.x, sa1);
                sb1 = f2fma(q1p[2*i+1], kk.y, sb1);
            }
            float x0, y0, x1, y1;
            f2unpack(f2add(sa0, sb0), x0, y0);
            f2unpack(f2add(sa1, sb1), x1, y1);
            float bj0 = (jj == 0) ? b0w.x : (jj == 1) ? b0w.y : (jj == 2) ? b0w.z : b0w.w;
            float bj1 = (jj == 0) ? b1w.x : (jj == 1) ? b1w.y : (jj == 2) ? b1w.z : b1w.w;

            float p0 = __expf(x0 + y0 + bj0);   // arg <= 0: never overflows
            float p1 = __expf(x1 + y1 + bj1);
            l0 += p0;
            l1 += p1;

            unsigned long long pp0 = f2pack(p0, p0);
            unsigned long long pp1 = f2pack(p1, p1);
            const ulonglong2* vrow = (const ulonglong2*)(vs + j * HD);
            #pragma unroll
            for (int i = 0; i < 8; i++) {
                ulonglong2 vv = vrow[i];
                acc0[2*i]   = f2fma(pp0, vv.x, acc0[2*i]);
                acc0[2*i+1] = f2fma(pp0, vv.y, acc0[2*i+1]);
                acc1[2*i]   = f2fma(pp1, vv.x, acc1[2*i]);
                acc1[2*i+1] = f2fma(pp1, vv.y, acc1[2*i+1]);
            }
        }
    }

    unsigned long long inv0 = f2pack(1.f / l0, 1.f / l0);
    unsigned long long inv1 = f2pack(1.f / l1, 1.f / l1);
    unsigned long long* op0 = (unsigned long long*)(g_att + ((size_t)(b * LQ + tid)) * CD + h * HD);
    unsigned long long* op1 = (unsigned long long*)(g_att + ((size_t)(b * LQ + tid + 128)) * CD + h * HD);
    #pragma unroll
    for (int i = 0; i < 16; i++) {
        op0[i] = f2mul(inv0, acc0[i]);
        op1[i] = f2mul(inv1, acc1[i]);
    }
}

// ---------------- projection GEMM: out = att @ proj_w^T + proj_b, f32x2 math ------
__global__ __launch_bounds__(256, 2) void proj_gemm_kernel(
    const float* __restrict__ W,     // proj_w (128,128)
    const float* __restrict__ pb,    // (128,)
    float* __restrict__ out)
{
    __shared__ float sm[64*36 + 128*36];
    float* As = sm;
    float* Ws = sm + 64*36;
    const int tid = threadIdx.x;
    const int r0 = blockIdx.x * 64;
    const int tr = tid >> 4, tc = tid & 15;
    const float* A = g_att;

    unsigned long long acc2[4][8];
    #pragma unroll
    for (int r = 0; r < 4; r++)
        #pragma unroll
        for (int i = 0; i < 8; i++) acc2[r][i] = 0ull;

    for (int kc = 0; kc < 4; kc++) {
        const int k0 = kc * 32;
        {
            int f = tid;
            #pragma unroll
            for (int rep = 0; rep < 2; rep++, f += 256) {
                int row = f >> 3, c4 = f & 7;
                float4 v = *(const float4*)(A + (size_t)(r0 + row) * CD + k0 + c4 * 4);
                float* d = As + row * 36 + c4 * 4;
                d[0] = v.x; d[1] = v.y; d[2] = v.z; d[3] = v.w;
            }
        }
        {
            int f = tid;
            #pragma unroll
            for (int rep = 0; rep < 4; rep++, f += 256) {
                int row = f >> 3, c4 = f & 7;
                float4 v = *(const float4*)(W + row * CD + k0 + c4 * 4);
                float* d = Ws + row * 36 + c4 * 4;
                d[0] = v.x; d[1] = v.y; d[2] = v.z; d[3] = v.w;
            }
        }
        __syncthreads();
        #pragma unroll
        for (int k4 = 0; k4 < 8; k4++) {
            ulonglong2 a2[4], b2[8];
            #pragma unroll
            for (int r = 0; r < 4; r++)
                a2[r] = *(const ulonglong2*)(As + (tr*4 + r) * 36 + k4 * 4);
            #pragma unroll
            for (int i = 0; i < 8; i++)
                b2[i] = *(const ulonglong2*)(Ws + (tc + 16*i) * 36 + k4 * 4);
            #pragma unroll
            for (int r = 0; r < 4; r++)
                #pragma unroll
                for (int i = 0; i < 8; i++) {
                    acc2[r][i] = f2fma(a2[r].x, b2[i].x, acc2[r][i]);
                    acc2[r][i] = f2fma(a2[r].y, b2[i].y, acc2[r][i]);
                }
        }
        __syncthreads();
    }

    #pragma unroll
    for (int r = 0; r < 4; r++) {
        int gr = r0 + tr*4 + r;
        #pragma unroll
        for (int i = 0; i < 8; i++) {
            int col = tc + 16*i;
            float lo, hi;
            f2unpack(acc2[r][i], lo, hi);
            out[(size_t)gr * CD + col] = lo + hi + pb[col];
        }
    }
}

// ---------------- launch ----------------
extern "C" void kernel_launch(void* const* d_in, const int* in_sizes, int n_in,
                              void* d_out, int out_size)
{
    (void)in_sizes; (void)n_in; (void)out_size;
    const float* x       = (const float*)d_in[0];
    const float* qkv_w   = (const float*)d_in[1];
    const float* q_bias  = (const float*)d_in[2];
    const float* v_bias  = (const float*)d_in[3];
    const float* lscale  = (const float*)d_in[4];
    const float* cpb_w1  = (const float*)d_in[5];
    const float* cpb_b1  = (const float*)d_in[6];
    const float* cpb_w2  = (const float*)d_in[7];
    const float* proj_w  = (const float*)d_in[8];
    const float* proj_b  = (const float*)d_in[9];
    const float* rtable  = (const float*)d_in[10];
    const int*   ridx    = (const int*)d_in[11];
    float* out = (float*)d_out;

    static const int attn_smem = 2 * LQ * HD * 4;   // 65536 bytes
    cudaFuncSetAttribute(attn_kernel, cudaFuncAttributeMaxDynamicSharedMemorySize, attn_smem);

    cpb_kernel<<<(MT + 31) / 32, 256>>>(rtable, cpb_w1, cpb_b1, cpb_w2);
    bias_gather_kernel<<<(NH * LQ * LQ) / 256, 256>>>(ridx, lscale);
    qkv_gemm_kernel<<<dim3((NW * LQ) / 64, 3), 256>>>(x, qkv_w, q_bias, v_bias, lscale);
    attn_kernel<<<NW * NH, 128, attn_smem>>>();
    proj_gemm_kernel<<<(NW * LQ) / 64, 256>>>(proj_w, proj_b, out);
}